// round 16
// baseline (speedup 1.0000x reference)
#include <cuda_runtime.h>
#include <cuda_fp16.h>
#include <math.h>
#include <stdint.h>

// ---------------------------------------------------------------------------
// Problem constants
// ---------------------------------------------------------------------------
#define BATCH   2
#define SEQ     2048
#define DMODEL  1024
#define HEADS   16
#define DHEAD   64
#define INNER   (HEADS * DHEAD)      // 1024
#define ROWS    (BATCH * SEQ)        // 4096
#define QKVW    (3 * INNER)          // 3072
#define ATTN_EPS 1e-8f

// ---------------------------------------------------------------------------
// Scratch (device globals)
// ---------------------------------------------------------------------------
__device__ __half g_xh  [ROWS * DMODEL];          // x fp16
__device__ __half g_w1  [QKVW * DMODEL];          // [Wq^T; Wkv^T] fp16
__device__ __half g_wot [DMODEL * INNER];         // Wo^T fp16
__device__ __half g_qkv [ROWS * QKVW];            // fused q|k|v fp16
__device__ __half g_ath [ROWS * INNER];           // attention out fp16

// ---------------------------------------------------------------------------
// Helpers (base ISA only)
// ---------------------------------------------------------------------------
__device__ __forceinline__ uint32_t smem_u32(const void* p) {
    uint32_t a;
    asm("{ .reg .u64 t; cvta.to.shared.u64 t, %1; cvt.u32.u64 %0, t; }"
        : "=r"(a) : "l"(p));
    return a;
}

__device__ __forceinline__ void ldmatrix_x4(uint32_t& r0, uint32_t& r1,
                                            uint32_t& r2, uint32_t& r3,
                                            uint32_t addr) {
    asm volatile("ldmatrix.sync.aligned.m8n8.x4.shared.b16 {%0,%1,%2,%3}, [%4];"
                 : "=r"(r0), "=r"(r1), "=r"(r2), "=r"(r3) : "r"(addr));
}

__device__ __forceinline__ void ldmatrix_x4_trans(uint32_t& r0, uint32_t& r1,
                                                  uint32_t& r2, uint32_t& r3,
                                                  uint32_t addr) {
    asm volatile("ldmatrix.sync.aligned.m8n8.x4.trans.shared.b16 {%0,%1,%2,%3}, [%4];"
                 : "=r"(r0), "=r"(r1), "=r"(r2), "=r"(r3) : "r"(addr));
}

__device__ __forceinline__ void mma_f16(float* d, const uint32_t* a, const uint32_t* b) {
    asm volatile(
        "mma.sync.aligned.m16n8k16.row.col.f32.f16.f16.f32 "
        "{%0,%1,%2,%3}, {%4,%5,%6,%7}, {%8,%9}, {%0,%1,%2,%3};"
        : "+f"(d[0]), "+f"(d[1]), "+f"(d[2]), "+f"(d[3])
        : "r"(a[0]), "r"(a[1]), "r"(a[2]), "r"(a[3]), "r"(b[0]), "r"(b[1]));
}

__device__ __forceinline__ void cp_async16(uint32_t saddr, const void* gaddr) {
    asm volatile("cp.async.cg.shared.global [%0], [%1], 16;"
                 :: "r"(saddr), "l"(gaddr));
}
__device__ __forceinline__ void cp_commit() {
    asm volatile("cp.async.commit_group;" ::: "memory");
}
template <int N>
__device__ __forceinline__ void cp_wait() {
    asm volatile("cp.async.wait_group %0;" :: "n"(N) : "memory");
}

__device__ __forceinline__ uint32_t sw64(uint32_t byte) {
    return byte ^ ((byte >> 3) & 0x30);
}

__device__ __forceinline__ uint32_t pack2(float a, float b) {
    __half2 H = __floats2half2_rn(a, b);
    return *(uint32_t*)&H;
}

// ---------------------------------------------------------------------------
// Fused prep kernel: blocks [0,4096) convert x -> fp16;
// blocks [4096,8192) transpose Wq / Wkv / Wo into fp16 [N,K].
// ---------------------------------------------------------------------------
#define PREP_SPLIT_BLOCKS 4096
#define PREP_TOTAL_BLOCKS 8192

__global__ __launch_bounds__(256)
void prep_kernel(const float* __restrict__ x,
                 __half* __restrict__ xh,
                 const float* __restrict__ Wq, const float* __restrict__ Wkv,
                 const float* __restrict__ Wo,
                 __half* __restrict__ w1, __half* __restrict__ wot)
{
    __shared__ float t[32][33];
    int bid = blockIdx.x;
    const int tid = threadIdx.x;

    if (bid < PREP_SPLIT_BLOCKS) {
        int i = bid * 256 + tid;
        float4 v = ((const float4*)x)[i];
        union { __half b[4]; uint2 u; } uh;
        uh.b[0] = __float2half_rn(v.x);
        uh.b[1] = __float2half_rn(v.y);
        uh.b[2] = __float2half_rn(v.z);
        uh.b[3] = __float2half_rn(v.w);
        ((uint2*)xh)[i] = uh.u;
        return;
    }

    bid -= PREP_SPLIT_BLOCKS;
    const float* W;
    __half* T;
    int K, N;
    if (bid < 1024)      { W = Wq;  T = w1;                              K = DMODEL; N = INNER; }
    else if (bid < 3072) { bid -= 1024; W = Wkv; T = w1 + (size_t)INNER * DMODEL; K = DMODEL; N = 2 * INNER; }
    else                 { bid -= 3072; W = Wo;  T = wot;                K = INNER;  N = DMODEL; }

    const int nbx = N / 32;
    const int bx = bid % nbx, by = bid / nbx;
    const int tx = tid & 31, ty = tid >> 5;

    int n  = bx * 32 + tx;
    int k0 = by * 32 + ty;
    #pragma unroll
    for (int i = 0; i < 32; i += 8)
        t[ty + i][tx] = W[(size_t)(k0 + i) * N + n];
    __syncthreads();
    int k  = by * 32 + tx;
    int n0 = bx * 32 + ty;
    #pragma unroll
    for (int i = 0; i < 32; i += 8)
        T[(size_t)(n0 + i) * K + k] = __float2half_rn(t[tx][ty + i]);
}

// ---------------------------------------------------------------------------
// HMMA GEMM core (1-term): C = Ah @ Bh^T, Bh [N,K] fp16.
// 128x128 CTA tile, 256 thr (2x4 warps, 64x32 each), BK=32, 4-stage cp.async.
// Stage = AH 8K + BH 8K = 16K; 4 stages = 64K -> 2 CTAs/SM.
// ---------------------------------------------------------------------------
#define STG1_BYTES  16384
#define OFF_BH1     8192
#define GEMM1_SMEM  (4 * STG1_BYTES)

struct GemmCtx {
    float acc[4][4][4];
    int wr, wc, lane;
};

__device__ __forceinline__ void gemm_core1(
    const __half* __restrict__ Ah, const __half* __restrict__ Bh,
    int K, int row0, int col0, GemmCtx& g)
{
    extern __shared__ char smraw[];
    const uint32_t sbase = smem_u32(smraw);

    const int tid  = threadIdx.x;
    const int wid  = tid >> 5;
    const int lane = tid & 31;
    g.wr = wid >> 2; g.wc = wid & 3; g.lane = lane;   // 2 x 4 warp grid

    const int nIter = K >> 5;
    const int lm_row = lane & 15;
    const int lm_koc = (lane >> 4) * 8;

    #pragma unroll
    for (int mf = 0; mf < 4; mf++)
        #pragma unroll
        for (int nf = 0; nf < 4; nf++)
            #pragma unroll
            for (int r = 0; r < 4; r++) g.acc[mf][nf][r] = 0.f;

    auto fill_stage = [&](int s, int kk0) {
        const uint32_t st = sbase + s * STG1_BYTES;
        #pragma unroll
        for (int it = 0; it < 2; it++) {
            int idx = tid + it * 256;
            int r = idx >> 2, c = idx & 3;
            uint32_t off = sw64((uint32_t)(r * 64 + c * 16));
            size_t ga = (size_t)(row0 + r) * K + kk0 + c * 8;
            cp_async16(st + off, Ah + ga);
        }
        #pragma unroll
        for (int it = 0; it < 2; it++) {
            int idx = tid + it * 256;
            int r = idx >> 2, c = idx & 3;
            uint32_t off = sw64((uint32_t)(r * 64 + c * 16));
            size_t gb = (size_t)(col0 + r) * K + kk0 + c * 8;
            cp_async16(st + OFF_BH1 + off, Bh + gb);
        }
    };

    fill_stage(0, 0);   cp_commit();
    fill_stage(1, 32);  cp_commit();
    fill_stage(2, 64);  cp_commit();

    for (int kt = 0; kt < nIter; kt++) {
        const int s = kt & 3;
        const uint32_t st = sbase + s * STG1_BYTES;

        cp_wait<2>();
        __syncthreads();

        if (kt + 3 < nIter) fill_stage((kt + 3) & 3, (kt + 3) * 32);
        cp_commit();

        #pragma unroll
        for (int ks = 0; ks < 2; ks++) {
            const int colb = (ks * 16 + lm_koc) * 2;
            uint32_t ah[4][4];

            #pragma unroll
            for (int mf = 0; mf < 4; mf++) {
                int r = g.wr * 64 + mf * 16 + lm_row;
                uint32_t off = sw64((uint32_t)(r * 64 + colb));
                ldmatrix_x4(ah[mf][0], ah[mf][1], ah[mf][2], ah[mf][3], st + off);
            }
            #pragma unroll
            for (int np = 0; np < 2; np++) {
                int r = g.wc * 32 + np * 16 + lm_row;
                uint32_t off = sw64((uint32_t)(r * 64 + colb));
                uint32_t r0, r1, r2, r3;
                uint32_t bh0[2], bh1[2];
                ldmatrix_x4(r0, r1, r2, r3, st + OFF_BH1 + off);
                bh0[0] = r0; bh0[1] = r2; bh1[0] = r1; bh1[1] = r3;
                #pragma unroll
                for (int mf = 0; mf < 4; mf++) {
                    mma_f16(g.acc[mf][2*np],   ah[mf], bh0);
                    mma_f16(g.acc[mf][2*np+1], ah[mf], bh1);
                }
            }
        }
        __syncthreads();
    }
}

// ---------------------------------------------------------------------------
// Merged q|k|v projection (one launch, 1-term, fp16 out; q cols scaled 0.125)
// ---------------------------------------------------------------------------
__global__ __launch_bounds__(256, 2)
void gemm_qkv(const __half* __restrict__ Ah, const __half* __restrict__ W,
              __half* __restrict__ O)
{
    const int row0 = blockIdx.y * 128;
    const int col0 = blockIdx.x * 128;

    GemmCtx g;
    gemm_core1(Ah, W, DMODEL, row0, col0, g);

    const int gq = g.lane >> 2;
    const int t4 = g.lane & 3;
    const float sc = (col0 < INNER) ? 0.125f : 1.0f;   // q tiles never straddle
    #pragma unroll
    for (int mf = 0; mf < 4; mf++) {
        int r0g = row0 + g.wr * 64 + mf * 16 + gq;
        #pragma unroll
        for (int nf = 0; nf < 4; nf++) {
            int cg = col0 + g.wc * 32 + nf * 8 + t4 * 2;
            *(uint32_t*)(O + (size_t)r0g * QKVW + cg)
                = pack2(g.acc[mf][nf][0] * sc, g.acc[mf][nf][1] * sc);
            *(uint32_t*)(O + (size_t)(r0g + 8) * QKVW + cg)
                = pack2(g.acc[mf][nf][2] * sc, g.acc[mf][nf][3] * sc);
        }
    }
}

// fp32-output GEMM (+bias) — final projection, 1-term A
__global__ __launch_bounds__(256, 2)
void gemm_out(const __half* __restrict__ Ah, const __half* __restrict__ Bh,
              const float* __restrict__ bias, float* __restrict__ C,
              int N, int K)
{
    GemmCtx g;
    const int row0 = blockIdx.y * 128;
    const int col0 = blockIdx.x * 128;
    gemm_core1(Ah, Bh, K, row0, col0, g);

    const int gq = g.lane >> 2;
    const int t4 = g.lane & 3;
    #pragma unroll
    for (int mf = 0; mf < 4; mf++) {
        int r0g = row0 + g.wr * 64 + mf * 16 + gq;
        #pragma unroll
        for (int nf = 0; nf < 4; nf++) {
            int cg = col0 + g.wc * 32 + nf * 8 + t4 * 2;
            float bx = bias[cg], by = bias[cg + 1];
            float2 v0 = { g.acc[mf][nf][0] + bx, g.acc[mf][nf][1] + by };
            float2 v1 = { g.acc[mf][nf][2] + bx, g.acc[mf][nf][3] + by };
            *(float2*)(C + (size_t)r0g * N + cg)       = v0;
            *(float2*)(C + (size_t)(r0g + 8) * N + cg) = v1;
        }
    }
}

// ---------------------------------------------------------------------------
// HMMA flash attention (fp16): 4 warps x 32 q-rows (Br=128, Bc=64).
// S = 1-term, PV = 1-term; fp32 accumulators. Q frags re-read from smem per
// tile (not hoisted) so regs fit 3 CTAs/SM. Stage KH 8K | VH 8K, dbl-buffered.
// Smem 50K -> 3 CTAs/SM (12 warps).
// ---------------------------------------------------------------------------
#define AT_Q_BYTES   16384
#define AT_STG_BYTES 16384
#define AT_SMEM      (1024 + AT_Q_BYTES + 2 * AT_STG_BYTES)

__global__ __launch_bounds__(128, 3)
void attn_mma(const __half* __restrict__ qkv, __half* __restrict__ goh)
{
    extern __shared__ char smraw[];
    const uint32_t b0a = smem_u32(smraw);
    const uint32_t sb = (b0a + 1023u) & ~1023u;

    const int tid = threadIdx.x;
    const int w = tid >> 5, lane = tid & 31;
    const int gq = lane >> 2, t4 = lane & 3;
    const int lm_row = lane & 15, lm_koc = (lane >> 4) * 8;
    const int vt = lane >> 3, vrl = lane & 7;
    const int b = blockIdx.y >> 4, h = blockIdx.y & 15;
    const int qt = gridDim.x - 1 - blockIdx.x;
    const int qstart = qt * 128;
    const int igmax = qstart + w * 32 + 31;

    const uint32_t QH = sb;
    const uint32_t ST0 = sb + AT_Q_BYTES;

    const size_t rowbase = (size_t)(b * SEQ) * QKVW + h * 64;

    // ---- Q fill (own cp.async group) ----
    #pragma unroll
    for (int it = 0; it < 8; it++) {
        int idx = tid + it * 128;                // 0..1023
        int r = idx >> 3, c = idx & 7;
        const __half* src = qkv + rowbase + (size_t)(qstart + r) * QKVW + c * 8;
        cp_async16(QH + (uint32_t)(r * 128 + ((c * 16) ^ ((r & 7) << 4))), src);
    }
    cp_commit();

    // ---- K/V stage fill: KH + VH ----
    auto fill_kv = [&](int s, int jstart) {
        const uint32_t st = ST0 + s * AT_STG_BYTES;
        #pragma unroll
        for (int it = 0; it < 8; it++) {
            int idx = tid + it * 128;            // 0..1023
            int tile = idx >> 9;                 // 0:KH 1:VH
            int r = (idx >> 3) & 63, c = idx & 7;
            int col = (tile ? 2048 : 1024) + c * 8;
            const __half* src = qkv + rowbase + (size_t)(jstart + r) * QKVW + col;
            cp_async16(st + (uint32_t)(tile * 8192 + r * 128 + ((c * 16) ^ ((r & 7) << 4))), src);
        }
    };

    fill_kv(0, 0);
    cp_commit();

    float o[2][8][4];
    float m[4] = { -INFINITY, -INFINITY, -INFINITY, -INFINITY };
    float lsum[4] = { 0.f, 0.f, 0.f, 0.f };
    #pragma unroll
    for (int mf = 0; mf < 2; mf++)
        #pragma unroll
        for (int nd = 0; nd < 8; nd++)
            #pragma unroll
            for (int r = 0; r < 4; r++) o[mf][nd][r] = 0.f;

    cp_wait<1>();          // Q resident (KV0 may stay pending)
    __syncthreads();

    const int nT = 2 * qt + 2;
    for (int jt = 0; jt < nT; jt++) {
        const int jstart = jt * 64;
        const uint32_t st = ST0 + (jt & 1) * AT_STG_BYTES;
        const uint32_t KH = st, VH = st + 8192;

        if (jt > 0) __syncthreads();
        if (jt + 1 < nT) {
            fill_kv((jt + 1) & 1, jstart + 64);
            cp_commit();
            cp_wait<1>();
        } else {
            cp_wait<0>();
        }
        __syncthreads();

        // ---- S = Q @ K^T (1-term; Q frags loaded from smem per kd) ----
        float s[2][8][4];
        #pragma unroll
        for (int mf = 0; mf < 2; mf++)
            #pragma unroll
            for (int nj = 0; nj < 8; nj++)
                #pragma unroll
                for (int r = 0; r < 4; r++) s[mf][nj][r] = 0.f;

        #pragma unroll
        for (int kd = 0; kd < 4; kd++) {
            const int cb = (kd * 16 + lm_koc) * 2;
            uint32_t qa[2][4];
            #pragma unroll
            for (int mf = 0; mf < 2; mf++) {
                int r = w * 32 + mf * 16 + lm_row;
                uint32_t off = (uint32_t)(r * 128 + (cb ^ ((r & 7) << 4)));
                ldmatrix_x4(qa[mf][0], qa[mf][1], qa[mf][2], qa[mf][3], QH + off);
            }
            #pragma unroll
            for (int jp = 0; jp < 4; jp++) {
                if (jstart + jp * 16 > igmax) continue;
                int r = jp * 16 + lm_row;
                uint32_t off = (uint32_t)(r * 128 + (cb ^ ((r & 7) << 4)));
                uint32_t r0, r1, r2, r3;
                uint32_t bh0[2], bh1[2];
                ldmatrix_x4(r0, r1, r2, r3, KH + off);
                bh0[0] = r0; bh0[1] = r2; bh1[0] = r1; bh1[1] = r3;
                #pragma unroll
                for (int mf = 0; mf < 2; mf++) {
                    mma_f16(s[mf][2*jp],   qa[mf], bh0);
                    mma_f16(s[mf][2*jp+1], qa[mf], bh1);
                }
            }
        }

        // ---- online softmax ----
        float alpha[4];
        #pragma unroll
        for (int mf = 0; mf < 2; mf++) {
            #pragma unroll
            for (int hh = 0; hh < 2; hh++) {
                const int hr = 2 * mf + hh;
                float mx = -INFINITY;
                #pragma unroll
                for (int nj = 0; nj < 8; nj++)
                    mx = fmaxf(mx, fmaxf(s[mf][nj][2*hh], s[mf][nj][2*hh+1]));
                mx = fmaxf(mx, __shfl_xor_sync(0xffffffffu, mx, 1));
                mx = fmaxf(mx, __shfl_xor_sync(0xffffffffu, mx, 2));
                float mn = fmaxf(m[hr], mx);
                alpha[hr] = __expf(m[hr] - mn);
                m[hr] = mn;
                const int ig = qstart + w * 32 + mf * 16 + hh * 8 + gq;
                float rs = 0.f;
                #pragma unroll
                for (int nj = 0; nj < 8; nj++) {
                    int jg = jstart + nj * 8 + t4 * 2;
                    float p0 = (jg     <= ig) ? __expf(s[mf][nj][2*hh]   - mn) : 0.f;
                    float p1 = (jg + 1 <= ig) ? __expf(s[mf][nj][2*hh+1] - mn) : 0.f;
                    s[mf][nj][2*hh] = p0; s[mf][nj][2*hh+1] = p1;
                    rs += p0 + p1;
                }
                rs += __shfl_xor_sync(0xffffffffu, rs, 1);
                rs += __shfl_xor_sync(0xffffffffu, rs, 2);
                lsum[hr] = lsum[hr] * alpha[hr] + rs;
            }
            #pragma unroll
            for (int nd = 0; nd < 8; nd++) {
                o[mf][nd][0] *= alpha[2*mf];     o[mf][nd][1] *= alpha[2*mf];
                o[mf][nd][2] *= alpha[2*mf + 1]; o[mf][nd][3] *= alpha[2*mf + 1];
            }
        }

        // ---- O += P @ V (1-term) ----
        #pragma unroll
        for (int kj = 0; kj < 4; kj++) {
            if (jstart + kj * 16 > igmax) continue;
            uint32_t ph[2][4];
            #pragma unroll
            for (int mf = 0; mf < 2; mf++) {
                ph[mf][0] = pack2(s[mf][2*kj][0],   s[mf][2*kj][1]);
                ph[mf][1] = pack2(s[mf][2*kj][2],   s[mf][2*kj][3]);
                ph[mf][2] = pack2(s[mf][2*kj+1][0], s[mf][2*kj+1][1]);
                ph[mf][3] = pack2(s[mf][2*kj+1][2], s[mf][2*kj+1][3]);
            }
            const int j = kj * 16 + (vt & 1) * 8 + vrl;
            const uint32_t jsw = (uint32_t)(j * 128);
            const int ch = (vt >> 1);
            #pragma unroll
            for (int ndp = 0; ndp < 4; ndp++) {
                int c = ndp * 2 + ch;
                uint32_t off = jsw + (uint32_t)((c * 16) ^ ((j & 7) << 4));
                uint32_t r0, r1, r2, r3;
                uint32_t bh0[2], bh1[2];
                ldmatrix_x4_trans(r0, r1, r2, r3, VH + off);
                bh0[0] = r0; bh0[1] = r1; bh1[0] = r2; bh1[1] = r3;
                #pragma unroll
                for (int mf = 0; mf < 2; mf++) {
                    mma_f16(o[mf][2*ndp],   ph[mf], bh0);
                    mma_f16(o[mf][2*ndp+1], ph[mf], bh1);
                }
            }
        }
    }

    // ---- epilogue: normalize, fp16 store ----
    #pragma unroll
    for (int mf = 0; mf < 2; mf++) {
        const float inv0 = 1.0f / (lsum[2*mf]     + ATTN_EPS);
        const float inv1 = 1.0f / (lsum[2*mf + 1] + ATTN_EPS);
        const size_t base0 = (size_t)(b * SEQ + qstart + w * 32 + mf * 16 + gq) * INNER
                           + h * 64 + t4 * 2;
        const size_t base1 = base0 + (size_t)8 * INNER;
        #pragma unroll
        for (int nd = 0; nd < 8; nd++) {
            *(uint32_t*)(goh + base0 + nd * 8) = pack2(o[mf][nd][0] * inv0,
                                                       o[mf][nd][1] * inv0);
            *(uint32_t*)(goh + base1 + nd * 8) = pack2(o[mf][nd][2] * inv1,
                                                       o[mf][nd][3] * inv1);
        }
    }
}

// ---------------------------------------------------------------------------
// Launch
// ---------------------------------------------------------------------------
extern "C" void kernel_launch(void* const* d_in, const int* in_sizes, int n_in,
                              void* d_out, int out_size)
{
    const float* x   = (const float*)d_in[0];
    const float* Wq  = (const float*)d_in[1];
    const float* Wkv = (const float*)d_in[2];
    const float* Wo  = (const float*)d_in[3];
    const float* bo  = (const float*)d_in[4];
    float* out = (float*)d_out;

    __half *pxh, *pw1, *pwo, *pqkv, *path;
    cudaGetSymbolAddress((void**)&pxh,  g_xh);
    cudaGetSymbolAddress((void**)&pw1,  g_w1);
    cudaGetSymbolAddress((void**)&pwo,  g_wot);
    cudaGetSymbolAddress((void**)&pqkv, g_qkv);
    cudaGetSymbolAddress((void**)&path, g_ath);

    cudaFuncSetAttribute(gemm_qkv,
                         cudaFuncAttributeMaxDynamicSharedMemorySize, GEMM1_SMEM);
    cudaFuncSetAttribute(gemm_out,
                         cudaFuncAttributeMaxDynamicSharedMemorySize, GEMM1_SMEM);
    cudaFuncSetAttribute(attn_mma,
                         cudaFuncAttributeMaxDynamicSharedMemorySize, AT_SMEM);

    // --- fused prep: x -> fp16 + all three weight transposes, one launch ---
    prep_kernel<<<PREP_TOTAL_BLOCKS, 256>>>(x, pxh, Wq, Wkv, Wo, pw1, pwo);

    // --- merged projection: q|k|v fp16 (q pre-scaled by 0.125) ---
    gemm_qkv<<<dim3(QKVW / 128, ROWS / 128), 256, GEMM1_SMEM>>>(pxh, pw1, pqkv);

    // --- attention (S 1-term, PV 1-term, fp16 out, 3 CTAs/SM) ---
    attn_mma<<<dim3(SEQ / 128, BATCH * HEADS), 128, AT_SMEM>>>(pqkv, path);

    // --- out = att @ Wo + bo (1-term) ---
    gemm_out<<<dim3(DMODEL / 128, ROWS / 128), 256, GEMM1_SMEM>>>(
        path, pwo, bo, out, DMODEL, INNER);
}

// round 17
// speedup vs baseline: 1.0982x; 1.0982x over previous
#include <cuda_runtime.h>
#include <cuda_fp16.h>
#include <math.h>
#include <stdint.h>

// ---------------------------------------------------------------------------
// Problem constants
// ---------------------------------------------------------------------------
#define BATCH   2
#define SEQ     2048
#define DMODEL  1024
#define HEADS   16
#define DHEAD   64
#define INNER   (HEADS * DHEAD)      // 1024
#define ROWS    (BATCH * SEQ)        // 4096
#define QKVW    (3 * INNER)          // 3072
#define ATTN_EPS 1e-8f

// ---------------------------------------------------------------------------
// Scratch (device globals)
// ---------------------------------------------------------------------------
__device__ __half g_xh  [ROWS * DMODEL];          // x fp16
__device__ __half g_w1  [QKVW * DMODEL];          // [Wq^T; Wkv^T] fp16
__device__ __half g_wot [DMODEL * INNER];         // Wo^T fp16
__device__ __half g_qkv [ROWS * QKVW];            // fused q|k|v fp16
__device__ __half g_ath [ROWS * INNER];           // attention out fp16

// ---------------------------------------------------------------------------
// Helpers (base ISA only)
// ---------------------------------------------------------------------------
__device__ __forceinline__ uint32_t smem_u32(const void* p) {
    uint32_t a;
    asm("{ .reg .u64 t; cvta.to.shared.u64 t, %1; cvt.u32.u64 %0, t; }"
        : "=r"(a) : "l"(p));
    return a;
}

__device__ __forceinline__ void ldmatrix_x4(uint32_t& r0, uint32_t& r1,
                                            uint32_t& r2, uint32_t& r3,
                                            uint32_t addr) {
    asm volatile("ldmatrix.sync.aligned.m8n8.x4.shared.b16 {%0,%1,%2,%3}, [%4];"
                 : "=r"(r0), "=r"(r1), "=r"(r2), "=r"(r3) : "r"(addr));
}

__device__ __forceinline__ void ldmatrix_x4_trans(uint32_t& r0, uint32_t& r1,
                                                  uint32_t& r2, uint32_t& r3,
                                                  uint32_t addr) {
    asm volatile("ldmatrix.sync.aligned.m8n8.x4.trans.shared.b16 {%0,%1,%2,%3}, [%4];"
                 : "=r"(r0), "=r"(r1), "=r"(r2), "=r"(r3) : "r"(addr));
}

__device__ __forceinline__ void mma_f16(float* d, const uint32_t* a, const uint32_t* b) {
    asm volatile(
        "mma.sync.aligned.m16n8k16.row.col.f32.f16.f16.f32 "
        "{%0,%1,%2,%3}, {%4,%5,%6,%7}, {%8,%9}, {%0,%1,%2,%3};"
        : "+f"(d[0]), "+f"(d[1]), "+f"(d[2]), "+f"(d[3])
        : "r"(a[0]), "r"(a[1]), "r"(a[2]), "r"(a[3]), "r"(b[0]), "r"(b[1]));
}

__device__ __forceinline__ void cp_async16(uint32_t saddr, const void* gaddr) {
    asm volatile("cp.async.cg.shared.global [%0], [%1], 16;"
                 :: "r"(saddr), "l"(gaddr));
}
__device__ __forceinline__ void cp_commit() {
    asm volatile("cp.async.commit_group;" ::: "memory");
}
template <int N>
__device__ __forceinline__ void cp_wait() {
    asm volatile("cp.async.wait_group %0;" :: "n"(N) : "memory");
}

__device__ __forceinline__ uint32_t sw64(uint32_t byte) {
    return byte ^ ((byte >> 3) & 0x30);
}

__device__ __forceinline__ uint32_t pack2(float a, float b) {
    __half2 H = __floats2half2_rn(a, b);
    return *(uint32_t*)&H;
}

// ---------------------------------------------------------------------------
// Fused prep kernel: blocks [0,4096) convert x -> fp16;
// blocks [4096,8192) transpose Wq / Wkv / Wo into fp16 [N,K].
// ---------------------------------------------------------------------------
#define PREP_SPLIT_BLOCKS 4096
#define PREP_TOTAL_BLOCKS 8192

__global__ __launch_bounds__(256)
void prep_kernel(const float* __restrict__ x,
                 __half* __restrict__ xh,
                 const float* __restrict__ Wq, const float* __restrict__ Wkv,
                 const float* __restrict__ Wo,
                 __half* __restrict__ w1, __half* __restrict__ wot)
{
    __shared__ float t[32][33];
    int bid = blockIdx.x;
    const int tid = threadIdx.x;

    if (bid < PREP_SPLIT_BLOCKS) {
        int i = bid * 256 + tid;
        float4 v = ((const float4*)x)[i];
        union { __half b[4]; uint2 u; } uh;
        uh.b[0] = __float2half_rn(v.x);
        uh.b[1] = __float2half_rn(v.y);
        uh.b[2] = __float2half_rn(v.z);
        uh.b[3] = __float2half_rn(v.w);
        ((uint2*)xh)[i] = uh.u;
        return;
    }

    bid -= PREP_SPLIT_BLOCKS;
    const float* W;
    __half* T;
    int K, N;
    if (bid < 1024)      { W = Wq;  T = w1;                              K = DMODEL; N = INNER; }
    else if (bid < 3072) { bid -= 1024; W = Wkv; T = w1 + (size_t)INNER * DMODEL; K = DMODEL; N = 2 * INNER; }
    else                 { bid -= 3072; W = Wo;  T = wot;                K = INNER;  N = DMODEL; }

    const int nbx = N / 32;
    const int bx = bid % nbx, by = bid / nbx;
    const int tx = tid & 31, ty = tid >> 5;

    int n  = bx * 32 + tx;
    int k0 = by * 32 + ty;
    #pragma unroll
    for (int i = 0; i < 32; i += 8)
        t[ty + i][tx] = W[(size_t)(k0 + i) * N + n];
    __syncthreads();
    int k  = by * 32 + tx;
    int n0 = bx * 32 + ty;
    #pragma unroll
    for (int i = 0; i < 32; i += 8)
        T[(size_t)(n0 + i) * K + k] = __float2half_rn(t[tx][ty + i]);
}

// ---------------------------------------------------------------------------
// HMMA GEMM core (1-term): C = Ah @ Bh^T, Bh [N,K] fp16.
// 128x128 CTA tile, 256 thr (2x4 warps, 64x32 each), BK=32, 4-stage cp.async.
// Stage = AH 8K + BH 8K = 16K; 4 stages = 64K -> 2 CTAs/SM.
// ---------------------------------------------------------------------------
#define STG1_BYTES  16384
#define OFF_BH1     8192
#define GEMM1_SMEM  (4 * STG1_BYTES)

struct GemmCtx {
    float acc[4][4][4];
    int wr, wc, lane;
};

__device__ __forceinline__ void gemm_core1(
    const __half* __restrict__ Ah, const __half* __restrict__ Bh,
    int K, int row0, int col0, GemmCtx& g)
{
    extern __shared__ char smraw[];
    const uint32_t sbase = smem_u32(smraw);

    const int tid  = threadIdx.x;
    const int wid  = tid >> 5;
    const int lane = tid & 31;
    g.wr = wid >> 2; g.wc = wid & 3; g.lane = lane;   // 2 x 4 warp grid

    const int nIter = K >> 5;
    const int lm_row = lane & 15;
    const int lm_koc = (lane >> 4) * 8;

    #pragma unroll
    for (int mf = 0; mf < 4; mf++)
        #pragma unroll
        for (int nf = 0; nf < 4; nf++)
            #pragma unroll
            for (int r = 0; r < 4; r++) g.acc[mf][nf][r] = 0.f;

    auto fill_stage = [&](int s, int kk0) {
        const uint32_t st = sbase + s * STG1_BYTES;
        #pragma unroll
        for (int it = 0; it < 2; it++) {
            int idx = tid + it * 256;
            int r = idx >> 2, c = idx & 3;
            uint32_t off = sw64((uint32_t)(r * 64 + c * 16));
            size_t ga = (size_t)(row0 + r) * K + kk0 + c * 8;
            cp_async16(st + off, Ah + ga);
        }
        #pragma unroll
        for (int it = 0; it < 2; it++) {
            int idx = tid + it * 256;
            int r = idx >> 2, c = idx & 3;
            uint32_t off = sw64((uint32_t)(r * 64 + c * 16));
            size_t gb = (size_t)(col0 + r) * K + kk0 + c * 8;
            cp_async16(st + OFF_BH1 + off, Bh + gb);
        }
    };

    fill_stage(0, 0);   cp_commit();
    fill_stage(1, 32);  cp_commit();
    fill_stage(2, 64);  cp_commit();

    for (int kt = 0; kt < nIter; kt++) {
        const int s = kt & 3;
        const uint32_t st = sbase + s * STG1_BYTES;

        cp_wait<2>();
        __syncthreads();

        if (kt + 3 < nIter) fill_stage((kt + 3) & 3, (kt + 3) * 32);
        cp_commit();

        #pragma unroll
        for (int ks = 0; ks < 2; ks++) {
            const int colb = (ks * 16 + lm_koc) * 2;
            uint32_t ah[4][4];

            #pragma unroll
            for (int mf = 0; mf < 4; mf++) {
                int r = g.wr * 64 + mf * 16 + lm_row;
                uint32_t off = sw64((uint32_t)(r * 64 + colb));
                ldmatrix_x4(ah[mf][0], ah[mf][1], ah[mf][2], ah[mf][3], st + off);
            }
            #pragma unroll
            for (int np = 0; np < 2; np++) {
                int r = g.wc * 32 + np * 16 + lm_row;
                uint32_t off = sw64((uint32_t)(r * 64 + colb));
                uint32_t r0, r1, r2, r3;
                uint32_t bh0[2], bh1[2];
                ldmatrix_x4(r0, r1, r2, r3, st + OFF_BH1 + off);
                bh0[0] = r0; bh0[1] = r2; bh1[0] = r1; bh1[1] = r3;
                #pragma unroll
                for (int mf = 0; mf < 4; mf++) {
                    mma_f16(g.acc[mf][2*np],   ah[mf], bh0);
                    mma_f16(g.acc[mf][2*np+1], ah[mf], bh1);
                }
            }
        }
        __syncthreads();
    }
}

// ---------------------------------------------------------------------------
// Merged q|k|v projection (one launch, 1-term, fp16 out; q cols scaled 0.125)
// ---------------------------------------------------------------------------
__global__ __launch_bounds__(256, 2)
void gemm_qkv(const __half* __restrict__ Ah, const __half* __restrict__ W,
              __half* __restrict__ O)
{
    const int row0 = blockIdx.y * 128;
    const int col0 = blockIdx.x * 128;

    GemmCtx g;
    gemm_core1(Ah, W, DMODEL, row0, col0, g);

    const int gq = g.lane >> 2;
    const int t4 = g.lane & 3;
    const float sc = (col0 < INNER) ? 0.125f : 1.0f;   // q tiles never straddle
    #pragma unroll
    for (int mf = 0; mf < 4; mf++) {
        int r0g = row0 + g.wr * 64 + mf * 16 + gq;
        #pragma unroll
        for (int nf = 0; nf < 4; nf++) {
            int cg = col0 + g.wc * 32 + nf * 8 + t4 * 2;
            *(uint32_t*)(O + (size_t)r0g * QKVW + cg)
                = pack2(g.acc[mf][nf][0] * sc, g.acc[mf][nf][1] * sc);
            *(uint32_t*)(O + (size_t)(r0g + 8) * QKVW + cg)
                = pack2(g.acc[mf][nf][2] * sc, g.acc[mf][nf][3] * sc);
        }
    }
}

// fp32-output GEMM (+bias) — final projection, 1-term A
__global__ __launch_bounds__(256, 2)
void gemm_out(const __half* __restrict__ Ah, const __half* __restrict__ Bh,
              const float* __restrict__ bias, float* __restrict__ C,
              int N, int K)
{
    GemmCtx g;
    const int row0 = blockIdx.y * 128;
    const int col0 = blockIdx.x * 128;
    gemm_core1(Ah, Bh, K, row0, col0, g);

    const int gq = g.lane >> 2;
    const int t4 = g.lane & 3;
    #pragma unroll
    for (int mf = 0; mf < 4; mf++) {
        int r0g = row0 + g.wr * 64 + mf * 16 + gq;
        #pragma unroll
        for (int nf = 0; nf < 4; nf++) {
            int cg = col0 + g.wc * 32 + nf * 8 + t4 * 2;
            float bx = bias[cg], by = bias[cg + 1];
            float2 v0 = { g.acc[mf][nf][0] + bx, g.acc[mf][nf][1] + by };
            float2 v1 = { g.acc[mf][nf][2] + bx, g.acc[mf][nf][3] + by };
            *(float2*)(C + (size_t)r0g * N + cg)       = v0;
            *(float2*)(C + (size_t)(r0g + 8) * N + cg) = v1;
        }
    }
}

// ---------------------------------------------------------------------------
// HMMA flash attention (fp16): 4 warps x 32 q-rows (Br=128, Bc=64).
// S = 1-term, PV = 1-term; fp32 accumulators. Q fragments hoisted into
// registers across the whole KV loop (round-15 proven config, 2 CTAs/SM).
// Stage: KH 8K | VH 8K = 16K, double-buffered. Smem 50K.
// ---------------------------------------------------------------------------
#define AT_Q_BYTES   16384
#define AT_STG_BYTES 16384
#define AT_SMEM      (1024 + AT_Q_BYTES + 2 * AT_STG_BYTES)

__global__ __launch_bounds__(128, 2)
void attn_mma(const __half* __restrict__ qkv, __half* __restrict__ goh)
{
    extern __shared__ char smraw[];
    const uint32_t b0a = smem_u32(smraw);
    const uint32_t sb = (b0a + 1023u) & ~1023u;

    const int tid = threadIdx.x;
    const int w = tid >> 5, lane = tid & 31;
    const int gq = lane >> 2, t4 = lane & 3;
    const int lm_row = lane & 15, lm_koc = (lane >> 4) * 8;
    const int vt = lane >> 3, vrl = lane & 7;
    const int b = blockIdx.y >> 4, h = blockIdx.y & 15;
    const int qt = gridDim.x - 1 - blockIdx.x;
    const int qstart = qt * 128;
    const int igmax = qstart + w * 32 + 31;

    const uint32_t QH = sb;
    const uint32_t ST0 = sb + AT_Q_BYTES;

    const size_t rowbase = (size_t)(b * SEQ) * QKVW + h * 64;

    // ---- Q fill (own cp.async group) ----
    #pragma unroll
    for (int it = 0; it < 8; it++) {
        int idx = tid + it * 128;                // 0..1023
        int r = idx >> 3, c = idx & 7;
        const __half* src = qkv + rowbase + (size_t)(qstart + r) * QKVW + c * 8;
        cp_async16(QH + (uint32_t)(r * 128 + ((c * 16) ^ ((r & 7) << 4))), src);
    }
    cp_commit();

    // ---- K/V stage fill: KH + VH ----
    auto fill_kv = [&](int s, int jstart) {
        const uint32_t st = ST0 + s * AT_STG_BYTES;
        #pragma unroll
        for (int it = 0; it < 8; it++) {
            int idx = tid + it * 128;            // 0..1023
            int tile = idx >> 9;                 // 0:KH 1:VH
            int r = (idx >> 3) & 63, c = idx & 7;
            int col = (tile ? 2048 : 1024) + c * 8;
            const __half* src = qkv + rowbase + (size_t)(jstart + r) * QKVW + col;
            cp_async16(st + (uint32_t)(tile * 8192 + r * 128 + ((c * 16) ^ ((r & 7) << 4))), src);
        }
    };

    fill_kv(0, 0);
    cp_commit();

    // ---- wait for Q (KV0 may stay pending), hoist Q frags ----
    cp_wait<1>();
    __syncthreads();

    uint32_t qa[2][4][4];                        // [mf][kd][reg]
    #pragma unroll
    for (int kd = 0; kd < 4; kd++) {
        const int cb = (kd * 16 + lm_koc) * 2;
        #pragma unroll
        for (int mf = 0; mf < 2; mf++) {
            int r = w * 32 + mf * 16 + lm_row;
            uint32_t off = (uint32_t)(r * 128 + (cb ^ ((r & 7) << 4)));
            ldmatrix_x4(qa[mf][kd][0], qa[mf][kd][1], qa[mf][kd][2], qa[mf][kd][3],
                        QH + off);
        }
    }

    float o[2][8][4];
    float m[4] = { -INFINITY, -INFINITY, -INFINITY, -INFINITY };
    float lsum[4] = { 0.f, 0.f, 0.f, 0.f };
    #pragma unroll
    for (int mf = 0; mf < 2; mf++)
        #pragma unroll
        for (int nd = 0; nd < 8; nd++)
            #pragma unroll
            for (int r = 0; r < 4; r++) o[mf][nd][r] = 0.f;

    const int nT = 2 * qt + 2;
    for (int jt = 0; jt < nT; jt++) {
        const int jstart = jt * 64;
        const uint32_t st = ST0 + (jt & 1) * AT_STG_BYTES;
        const uint32_t KH = st, VH = st + 8192;

        if (jt > 0) __syncthreads();
        if (jt + 1 < nT) {
            fill_kv((jt + 1) & 1, jstart + 64);
            cp_commit();
            cp_wait<1>();
        } else {
            cp_wait<0>();
        }
        __syncthreads();

        // ---- S = Q @ K^T (1-term) ----
        float s[2][8][4];
        #pragma unroll
        for (int mf = 0; mf < 2; mf++)
            #pragma unroll
            for (int nj = 0; nj < 8; nj++)
                #pragma unroll
                for (int r = 0; r < 4; r++) s[mf][nj][r] = 0.f;

        #pragma unroll
        for (int kd = 0; kd < 4; kd++) {
            const int cb = (kd * 16 + lm_koc) * 2;
            #pragma unroll
            for (int jp = 0; jp < 4; jp++) {
                if (jstart + jp * 16 > igmax) continue;
                int r = jp * 16 + lm_row;
                uint32_t off = (uint32_t)(r * 128 + (cb ^ ((r & 7) << 4)));
                uint32_t r0, r1, r2, r3;
                uint32_t bh0[2], bh1[2];
                ldmatrix_x4(r0, r1, r2, r3, KH + off);
                bh0[0] = r0; bh0[1] = r2; bh1[0] = r1; bh1[1] = r3;
                #pragma unroll
                for (int mf = 0; mf < 2; mf++) {
                    mma_f16(s[mf][2*jp],   qa[mf][kd], bh0);
                    mma_f16(s[mf][2*jp+1], qa[mf][kd], bh1);
                }
            }
        }

        // ---- online softmax ----
        float alpha[4];
        #pragma unroll
        for (int mf = 0; mf < 2; mf++) {
            #pragma unroll
            for (int hh = 0; hh < 2; hh++) {
                const int hr = 2 * mf + hh;
                float mx = -INFINITY;
                #pragma unroll
                for (int nj = 0; nj < 8; nj++)
                    mx = fmaxf(mx, fmaxf(s[mf][nj][2*hh], s[mf][nj][2*hh+1]));
                mx = fmaxf(mx, __shfl_xor_sync(0xffffffffu, mx, 1));
                mx = fmaxf(mx, __shfl_xor_sync(0xffffffffu, mx, 2));
                float mn = fmaxf(m[hr], mx);
                alpha[hr] = __expf(m[hr] - mn);
                m[hr] = mn;
                const int ig = qstart + w * 32 + mf * 16 + hh * 8 + gq;
                float rs = 0.f;
                #pragma unroll
                for (int nj = 0; nj < 8; nj++) {
                    int jg = jstart + nj * 8 + t4 * 2;
                    float p0 = (jg     <= ig) ? __expf(s[mf][nj][2*hh]   - mn) : 0.f;
                    float p1 = (jg + 1 <= ig) ? __expf(s[mf][nj][2*hh+1] - mn) : 0.f;
                    s[mf][nj][2*hh] = p0; s[mf][nj][2*hh+1] = p1;
                    rs += p0 + p1;
                }
                rs += __shfl_xor_sync(0xffffffffu, rs, 1);
                rs += __shfl_xor_sync(0xffffffffu, rs, 2);
                lsum[hr] = lsum[hr] * alpha[hr] + rs;
            }
            #pragma unroll
            for (int nd = 0; nd < 8; nd++) {
                o[mf][nd][0] *= alpha[2*mf];     o[mf][nd][1] *= alpha[2*mf];
                o[mf][nd][2] *= alpha[2*mf + 1]; o[mf][nd][3] *= alpha[2*mf + 1];
            }
        }

        // ---- O += P @ V (1-term) ----
        #pragma unroll
        for (int kj = 0; kj < 4; kj++) {
            if (jstart + kj * 16 > igmax) continue;
            uint32_t ph[2][4];
            #pragma unroll
            for (int mf = 0; mf < 2; mf++) {
                ph[mf][0] = pack2(s[mf][2*kj][0],   s[mf][2*kj][1]);
                ph[mf][1] = pack2(s[mf][2*kj][2],   s[mf][2*kj][3]);
                ph[mf][2] = pack2(s[mf][2*kj+1][0], s[mf][2*kj+1][1]);
                ph[mf][3] = pack2(s[mf][2*kj+1][2], s[mf][2*kj+1][3]);
            }
            const int j = kj * 16 + (vt & 1) * 8 + vrl;
            const uint32_t jsw = (uint32_t)(j * 128);
            const int ch = (vt >> 1);
            #pragma unroll
            for (int ndp = 0; ndp < 4; ndp++) {
                int c = ndp * 2 + ch;
                uint32_t off = jsw + (uint32_t)((c * 16) ^ ((j & 7) << 4));
                uint32_t r0, r1, r2, r3;
                uint32_t bh0[2], bh1[2];
                ldmatrix_x4_trans(r0, r1, r2, r3, VH + off);
                bh0[0] = r0; bh0[1] = r1; bh1[0] = r2; bh1[1] = r3;
                #pragma unroll
                for (int mf = 0; mf < 2; mf++) {
                    mma_f16(o[mf][2*ndp],   ph[mf], bh0);
                    mma_f16(o[mf][2*ndp+1], ph[mf], bh1);
                }
            }
        }
    }

    // ---- epilogue: normalize, fp16 store ----
    #pragma unroll
    for (int mf = 0; mf < 2; mf++) {
        const float inv0 = 1.0f / (lsum[2*mf]     + ATTN_EPS);
        const float inv1 = 1.0f / (lsum[2*mf + 1] + ATTN_EPS);
        const size_t base0 = (size_t)(b * SEQ + qstart + w * 32 + mf * 16 + gq) * INNER
                           + h * 64 + t4 * 2;
        const size_t base1 = base0 + (size_t)8 * INNER;
        #pragma unroll
        for (int nd = 0; nd < 8; nd++) {
            *(uint32_t*)(goh + base0 + nd * 8) = pack2(o[mf][nd][0] * inv0,
                                                       o[mf][nd][1] * inv0);
            *(uint32_t*)(goh + base1 + nd * 8) = pack2(o[mf][nd][2] * inv1,
                                                       o[mf][nd][3] * inv1);
        }
    }
}

// ---------------------------------------------------------------------------
// Launch
// ---------------------------------------------------------------------------
extern "C" void kernel_launch(void* const* d_in, const int* in_sizes, int n_in,
                              void* d_out, int out_size)
{
    const float* x   = (const float*)d_in[0];
    const float* Wq  = (const float*)d_in[1];
    const float* Wkv = (const float*)d_in[2];
    const float* Wo  = (const float*)d_in[3];
    const float* bo  = (const float*)d_in[4];
    float* out = (float*)d_out;

    __half *pxh, *pw1, *pwo, *pqkv, *path;
    cudaGetSymbolAddress((void**)&pxh,  g_xh);
    cudaGetSymbolAddress((void**)&pw1,  g_w1);
    cudaGetSymbolAddress((void**)&pwo,  g_wot);
    cudaGetSymbolAddress((void**)&pqkv, g_qkv);
    cudaGetSymbolAddress((void**)&path, g_ath);

    cudaFuncSetAttribute(gemm_qkv,
                         cudaFuncAttributeMaxDynamicSharedMemorySize, GEMM1_SMEM);
    cudaFuncSetAttribute(gemm_out,
                         cudaFuncAttributeMaxDynamicSharedMemorySize, GEMM1_SMEM);
    cudaFuncSetAttribute(attn_mma,
                         cudaFuncAttributeMaxDynamicSharedMemorySize, AT_SMEM);

    // --- fused prep: x -> fp16 + all three weight transposes, one launch ---
    prep_kernel<<<PREP_TOTAL_BLOCKS, 256>>>(x, pxh, Wq, Wkv, Wo, pw1, pwo);

    // --- merged projection: q|k|v fp16 (q pre-scaled by 0.125) ---
    gemm_qkv<<<dim3(QKVW / 128, ROWS / 128), 256, GEMM1_SMEM>>>(pxh, pw1, pqkv);

    // --- attention (S 1-term, PV 1-term, fp16 out, 2 CTAs/SM, hoisted Q) ---
    attn_mma<<<dim3(SEQ / 128, BATCH * HEADS), 128, AT_SMEM>>>(pqkv, path);

    // --- out = att @ Wo + bo (1-term) ---
    gemm_out<<<dim3(DMODEL / 128, ROWS / 128), 256, GEMM1_SMEM>>>(
        path, pwo, bo, out, DMODEL, INNER);
}